// round 1
// baseline (speedup 1.0000x reference)
#include <cuda_runtime.h>
#include <math.h>

#define NB 8
#define NN 1024
#define ND 128
#define NP 16
#define KA 2048           // P*D joint contraction dim for attention
#define EPSF 1e-5f
#define NTILE 8           // 1024/128
#define NPAIRS 36         // 8*9/2 symmetric tile pairs

// Scratch (module-load allocated; no runtime allocation)
__device__ __align__(16) float g_A[NB * NN * KA];    // 64 MB: normalized context*w, scaled 1/sqrt(P)
__device__ __align__(16) float g_SW[NB * NN * NN];   // 32 MB: row-normalized selfwind
__device__ __align__(16) float g_Y[NB * NN * NN];    // 32 MB: gamma*SW.SW^T/20 + EPS (pre row-norm)

// ---------------------------------------------------------------------------
// Kernel 1: build A[b,n,p*128+d] = context[b,n,d]*w[p,d] / (sqrt(P)*max(||c*w_p||,1e-12))
// 1 warp per (b,n) row; lane handles 4 d's as float4.
// ---------------------------------------------------------------------------
__global__ void __launch_bounds__(128) build_A_kernel(
    const float* __restrict__ context, const float* __restrict__ weight)
{
    __shared__ float wsh[NP * ND];
    int tid = threadIdx.x;
    #pragma unroll
    for (int i = tid; i < NP * ND; i += 128) wsh[i] = weight[i];
    __syncthreads();

    int warp = tid >> 5, lane = tid & 31;
    int row = blockIdx.x * 4 + warp;                 // flat (b,n), 8192 total
    const float4* ctx4 = reinterpret_cast<const float4*>(context + (size_t)row * ND);
    float4 c = ctx4[lane];
    const float4* w4 = reinterpret_cast<const float4*>(wsh);
    float4* A4 = reinterpret_cast<float4*>(g_A + (size_t)row * KA);

    #pragma unroll
    for (int p = 0; p < NP; p++) {
        float4 wv = w4[p * 32 + lane];
        float4 pr;
        pr.x = c.x * wv.x; pr.y = c.y * wv.y; pr.z = c.z * wv.z; pr.w = c.w * wv.w;
        float s = pr.x * pr.x + pr.y * pr.y + pr.z * pr.z + pr.w * pr.w;
        #pragma unroll
        for (int o = 16; o > 0; o >>= 1) s += __shfl_xor_sync(0xffffffffu, s, o);
        float inv = 0.25f / fmaxf(sqrtf(s), 1e-12f);  // 0.25 = 1/sqrt(P)
        float4 ov; ov.x = pr.x * inv; ov.y = pr.y * inv; ov.z = pr.z * inv; ov.w = pr.w * inv;
        A4[p * 32 + lane] = ov;
    }
}

// ---------------------------------------------------------------------------
// Kernel 2: selfwind rows, L2-normalized along m.
// 1 block (256 thr) per (b,n) row; each thread 4 m's.
// ---------------------------------------------------------------------------
__global__ void __launch_bounds__(256) selfwind_kernel(
    const float* __restrict__ acc_u, const float* __restrict__ acc_v,
    const float* __restrict__ uv_angle, const float* __restrict__ uv_angleACC,
    const float* __restrict__ speed,
    const float* __restrict__ dist, const float* __restrict__ angle)
{
    int row = blockIdx.x;          // b*N + n
    int n = row & (NN - 1);
    int tid = threadIdx.x;

    float uva = uv_angle[row];
    float au = acc_u[row], av = acc_v[row];
    float tacc = sqrtf(au * au + av * av + EPSF) * fabsf(cosf(uv_angleACC[row] - uva));
    float spd = fabsf(speed[row]);

    float vals[4];
    float ssum = 0.0f;
    #pragma unroll
    for (int j = 0; j < 4; j++) {
        int m = tid + j * 256;
        float a = angle[n * NN + m];
        float dd = dist[n * NN + m] + EPSF;
        float diag = (m == n) ? 0.5f * tacc : 0.0f;   // sigma = 0.5
        float v = spd * fabsf(cosf(a - uva) + diag) / dd;
        vals[j] = v;
        ssum += v * v;
    }
    __shared__ float red[8];
    #pragma unroll
    for (int o = 16; o > 0; o >>= 1) ssum += __shfl_xor_sync(0xffffffffu, ssum, o);
    if ((tid & 31) == 0) red[tid >> 5] = ssum;
    __syncthreads();
    float tot = 0.0f;
    #pragma unroll
    for (int w = 0; w < 8; w++) tot += red[w];
    float inv = 1.0f / fmaxf(sqrtf(tot), 1e-12f);

    float* swrow = g_SW + (size_t)row * NN;
    #pragma unroll
    for (int j = 0; j < 4; j++) swrow[tid + j * 256] = vals[j] * inv;
}

// ---------------------------------------------------------------------------
// Kernel 3: symmetric batched SYRK with per-mode epilogue.
// MODE 0: C = relu-mask(A A^T), K=2048, C = d_out (masked attention)
// MODE 1: C = 0.07*(SW SW^T) + EPS, K=1024, C = g_Y
// 128x128 tile per block, 256 threads, 8x8 per thread, BK=16.
// Only lower-triangular tile pairs computed; both (n,m) and (m,n) written.
// ---------------------------------------------------------------------------
template <int MODE>
__global__ void __launch_bounds__(256, 2) syrk_kernel(float* __restrict__ Cout)
{
    const int K = (MODE == 0) ? KA : NN;
    const float* __restrict__ X = (MODE == 0) ? g_A : g_SW;
    float* __restrict__ C = (MODE == 0) ? Cout : g_Y;

    int pair = blockIdx.x % NPAIRS;
    int b = blockIdx.x / NPAIRS;
    int ti = 0;
    while (pair >= ti + 1) { pair -= (ti + 1); ti++; }
    int tj = pair;                                     // tj <= ti

    const float* Xm = X + ((size_t)b * NN + ti * 128) * K;
    const float* Xn = X + ((size_t)b * NN + tj * 128) * K;

    __shared__ float As[16 * 128];
    __shared__ float Bs[16 * 128];

    int tid = threadIdx.x;
    int tm = tid >> 4, tn = tid & 15;

    float acc[8][8];
    #pragma unroll
    for (int i = 0; i < 8; i++)
        #pragma unroll
        for (int j = 0; j < 8; j++) acc[i][j] = 0.0f;

    for (int kt = 0; kt < K; kt += 16) {
        #pragma unroll
        for (int q = 0; q < 2; q++) {
            int idx = tid + q * 256;                   // 512 float4 = 128 rows x 4
            int r = idx >> 2, c4 = idx & 3;
            float4 va = *reinterpret_cast<const float4*>(Xm + (size_t)r * K + kt + c4 * 4);
            float4 vb = *reinterpret_cast<const float4*>(Xn + (size_t)r * K + kt + c4 * 4);
            As[(c4 * 4 + 0) * 128 + r] = va.x;
            As[(c4 * 4 + 1) * 128 + r] = va.y;
            As[(c4 * 4 + 2) * 128 + r] = va.z;
            As[(c4 * 4 + 3) * 128 + r] = va.w;
            Bs[(c4 * 4 + 0) * 128 + r] = vb.x;
            Bs[(c4 * 4 + 1) * 128 + r] = vb.y;
            Bs[(c4 * 4 + 2) * 128 + r] = vb.z;
            Bs[(c4 * 4 + 3) * 128 + r] = vb.w;
        }
        __syncthreads();
        #pragma unroll
        for (int kk = 0; kk < 16; kk++) {
            float4 a0 = *reinterpret_cast<float4*>(&As[kk * 128 + tm * 8]);
            float4 a1 = *reinterpret_cast<float4*>(&As[kk * 128 + tm * 8 + 4]);
            float4 b0 = *reinterpret_cast<float4*>(&Bs[kk * 128 + tn * 8]);
            float4 b1 = *reinterpret_cast<float4*>(&Bs[kk * 128 + tn * 8 + 4]);
            float a[8] = {a0.x, a0.y, a0.z, a0.w, a1.x, a1.y, a1.z, a1.w};
            float bb[8] = {b0.x, b0.y, b0.z, b0.w, b1.x, b1.y, b1.z, b1.w};
            #pragma unroll
            for (int i = 0; i < 8; i++)
                #pragma unroll
                for (int j = 0; j < 8; j++)
                    acc[i][j] = fmaf(a[i], bb[j], acc[i][j]);
        }
        __syncthreads();
    }

    size_t cb = (size_t)b * NN * NN;
    #pragma unroll
    for (int i = 0; i < 8; i++) {
        int gm = ti * 128 + tm * 8 + i;
        #pragma unroll
        for (int j = 0; j < 8; j++) {
            int gn = tj * 128 + tn * 8 + j;
            float v = acc[i][j];
            if (MODE == 0) v = (v > 0.0f) ? v : 0.0f;              // attention mask
            else           v = 0.07f * v + EPSF;                   // gamma/20 * dot + EPS
            C[cb + (size_t)gm * NN + gn] = v;
            C[cb + (size_t)gn * NN + gm] = v;                      // symmetric mirror
        }
    }
}

// ---------------------------------------------------------------------------
// Kernel 4: per-row: y = l2norm(Y); u = l2norm(|theta*SW + sqrt(y)| + EPS);
//           out = masked_attention (already in d_out) * u.
// 1 block (256 thr) per (b,n) row; each thread 4 m's.
// ---------------------------------------------------------------------------
__global__ void __launch_bounds__(256) final_kernel(float* __restrict__ out)
{
    int row = blockIdx.x;
    int tid = threadIdx.x;
    const float* yrow = g_Y + (size_t)row * NN;
    const float* swrow = g_SW + (size_t)row * NN;
    float* orow = out + (size_t)row * NN;

    __shared__ float red[8];

    float yv[4];
    float s1 = 0.0f;
    #pragma unroll
    for (int j = 0; j < 4; j++) {
        float y = yrow[tid + j * 256];
        yv[j] = y;
        s1 += y * y;
    }
    #pragma unroll
    for (int o = 16; o > 0; o >>= 1) s1 += __shfl_xor_sync(0xffffffffu, s1, o);
    if ((tid & 31) == 0) red[tid >> 5] = s1;
    __syncthreads();
    float yt = 0.0f;
    #pragma unroll
    for (int w = 0; w < 8; w++) yt += red[w];
    float yin = 1.0f / fmaxf(sqrtf(yt), 1e-12f);
    __syncthreads();   // protect red[] before reuse

    float tv[4];
    float s2 = 0.0f;
    #pragma unroll
    for (int j = 0; j < 4; j++) {
        float t = fabsf(0.5f * swrow[tid + j * 256] + sqrtf(yv[j] * yin)) + EPSF; // theta=0.5
        tv[j] = t;
        s2 += t * t;
    }
    #pragma unroll
    for (int o = 16; o > 0; o >>= 1) s2 += __shfl_xor_sync(0xffffffffu, s2, o);
    if ((tid & 31) == 0) red[tid >> 5] = s2;
    __syncthreads();
    float tt = 0.0f;
    #pragma unroll
    for (int w = 0; w < 8; w++) tt += red[w];
    float tin = 1.0f / fmaxf(sqrtf(tt), 1e-12f);

    #pragma unroll
    for (int j = 0; j < 4; j++) {
        int m = tid + j * 256;
        orow[m] = orow[m] * (tv[j] * tin);
    }
}

// ---------------------------------------------------------------------------
extern "C" void kernel_launch(void* const* d_in, const int* in_sizes, int n_in,
                              void* d_out, int out_size)
{
    const float* context     = (const float*)d_in[0];  // (8,1024,128)
    const float* acc_u       = (const float*)d_in[1];  // (8,1024,1)
    const float* acc_v       = (const float*)d_in[2];
    const float* uv_angle    = (const float*)d_in[3];
    const float* uv_angleACC = (const float*)d_in[4];
    const float* speed       = (const float*)d_in[5];
    // d_in[6] = isPhy (unused by the reference math)
    const float* dist        = (const float*)d_in[7];  // (1024,1024)
    const float* angle       = (const float*)d_in[8];  // (1024,1024)
    const float* weight      = (const float*)d_in[9];  // (16,128)
    float* out = (float*)d_out;                        // (8,1024,1024)

    build_A_kernel<<<NB * NN / 4, 128>>>(context, weight);
    selfwind_kernel<<<NB * NN, 256>>>(acc_u, acc_v, uv_angle, uv_angleACC, speed, dist, angle);
    syrk_kernel<0><<<NB * NPAIRS, 256>>>(out);   // masked attention -> d_out
    syrk_kernel<1><<<NB * NPAIRS, 256>>>(out);   // writes g_Y internally
    final_kernel<<<NB * NN, 256>>>(out);
}

// round 3
// speedup vs baseline: 2.2665x; 2.2665x over previous
#include <cuda_runtime.h>
#include <cuda_bf16.h>
#include <math.h>
#include <stdint.h>

#define NB 8
#define NN 1024
#define ND 128
#define NP 16
#define KA 2048           // P*D joint contraction dim for attention
#define EPSF 1e-5f
#define NPAIRS 36         // 8*9/2 symmetric tile pairs

// ---------------------------------------------------------------------------
// Scratch (module-load allocated; no runtime allocation)
// ---------------------------------------------------------------------------
__device__ __align__(16) __nv_bfloat16 g_Ah[(size_t)NB * NN * KA];   // 32 MB
__device__ __align__(16) __nv_bfloat16 g_Al[(size_t)NB * NN * KA];   // 32 MB
__device__ __align__(16) float         g_SW[(size_t)NB * NN * NN];   // 32 MB
__device__ __align__(16) __nv_bfloat16 g_SWh[(size_t)NB * NN * NN];  // 16 MB
__device__ __align__(16) __nv_bfloat16 g_SWl[(size_t)NB * NN * NN];  // 16 MB
__device__ __align__(16) float         g_Y[(size_t)NB * NN * NN];    // 32 MB

__device__ __forceinline__ uint32_t smem_u32(const void* p) {
    uint32_t a;
    asm("{ .reg .u64 t; cvta.to.shared.u64 t, %1; cvt.u32.u64 %0, t; }"
        : "=r"(a) : "l"(p));
    return a;
}

__device__ __forceinline__ uint32_t pack_bf2(__nv_bfloat16 a, __nv_bfloat16 b) {
    return (uint32_t)__bfloat16_as_ushort(a) | ((uint32_t)__bfloat16_as_ushort(b) << 16);
}

__device__ __forceinline__ void ldsm4(uint32_t* r, uint32_t addr) {
    asm volatile("ldmatrix.sync.aligned.m8n8.x4.shared.b16 {%0,%1,%2,%3}, [%4];"
                 : "=r"(r[0]), "=r"(r[1]), "=r"(r[2]), "=r"(r[3]) : "r"(addr));
}

__device__ __forceinline__ void mma16816(float* c, const uint32_t* a,
                                         uint32_t b0, uint32_t b1) {
    asm volatile(
        "mma.sync.aligned.m16n8k16.row.col.f32.bf16.bf16.f32 "
        "{%0,%1,%2,%3}, {%4,%5,%6,%7}, {%8,%9}, {%0,%1,%2,%3};"
        : "+f"(c[0]), "+f"(c[1]), "+f"(c[2]), "+f"(c[3])
        : "r"(a[0]), "r"(a[1]), "r"(a[2]), "r"(a[3]), "r"(b0), "r"(b1));
}

// ---------------------------------------------------------------------------
// Kernel 1: hi/lo bf16 split of A[b,n,p*128+d] = ctx*w / (sqrt(P)*||c*w_p||)
// ---------------------------------------------------------------------------
__global__ void __launch_bounds__(128) build_A_kernel(
    const float* __restrict__ context, const float* __restrict__ weight)
{
    __shared__ float wsh[NP * ND];
    int tid = threadIdx.x;
    #pragma unroll
    for (int i = tid; i < NP * ND; i += 128) wsh[i] = weight[i];
    __syncthreads();

    int warp = tid >> 5, lane = tid & 31;
    int row = blockIdx.x * 4 + warp;
    const float4* ctx4 = reinterpret_cast<const float4*>(context + (size_t)row * ND);
    float4 c = ctx4[lane];
    const float4* w4 = reinterpret_cast<const float4*>(wsh);
    uint2* Ah2 = reinterpret_cast<uint2*>(g_Ah + (size_t)row * KA);
    uint2* Al2 = reinterpret_cast<uint2*>(g_Al + (size_t)row * KA);

    #pragma unroll
    for (int p = 0; p < NP; p++) {
        float4 wv = w4[p * 32 + lane];
        float4 pr;
        pr.x = c.x * wv.x; pr.y = c.y * wv.y; pr.z = c.z * wv.z; pr.w = c.w * wv.w;
        float s = pr.x * pr.x + pr.y * pr.y + pr.z * pr.z + pr.w * pr.w;
        #pragma unroll
        for (int o = 16; o > 0; o >>= 1) s += __shfl_xor_sync(0xffffffffu, s, o);
        float inv = 0.25f / fmaxf(sqrtf(s), 1e-12f);   // 0.25 = 1/sqrt(P)
        float v0 = pr.x * inv, v1 = pr.y * inv, v2 = pr.z * inv, v3 = pr.w * inv;
        __nv_bfloat16 h0 = __float2bfloat16(v0), h1 = __float2bfloat16(v1);
        __nv_bfloat16 h2 = __float2bfloat16(v2), h3 = __float2bfloat16(v3);
        uint2 hv; hv.x = pack_bf2(h0, h1); hv.y = pack_bf2(h2, h3);
        Ah2[p * 32 + lane] = hv;
        __nv_bfloat16 l0 = __float2bfloat16(v0 - __bfloat162float(h0));
        __nv_bfloat16 l1 = __float2bfloat16(v1 - __bfloat162float(h1));
        __nv_bfloat16 l2 = __float2bfloat16(v2 - __bfloat162float(h2));
        __nv_bfloat16 l3 = __float2bfloat16(v3 - __bfloat162float(h3));
        uint2 lv; lv.x = pack_bf2(l0, l1); lv.y = pack_bf2(l2, l3);
        Al2[p * 32 + lane] = lv;
    }
}

// ---------------------------------------------------------------------------
// Kernel 2: selfwind rows, L2-normalized; writes fp32 + hi/lo bf16.
// ---------------------------------------------------------------------------
__global__ void __launch_bounds__(256) selfwind_kernel(
    const float* __restrict__ acc_u, const float* __restrict__ acc_v,
    const float* __restrict__ uv_angle, const float* __restrict__ uv_angleACC,
    const float* __restrict__ speed,
    const float* __restrict__ dist, const float* __restrict__ angle)
{
    int row = blockIdx.x;          // b*N + n
    int n = row & (NN - 1);
    int tid = threadIdx.x;

    float uva = uv_angle[row];
    float au = acc_u[row], av = acc_v[row];
    float tacc = sqrtf(au * au + av * av + EPSF) * fabsf(cosf(uv_angleACC[row] - uva));
    float spd = fabsf(speed[row]);

    float vals[4];
    float ssum = 0.0f;
    #pragma unroll
    for (int j = 0; j < 4; j++) {
        int m = tid + j * 256;
        float a = angle[n * NN + m];
        float dd = dist[n * NN + m] + EPSF;
        float diag = (m == n) ? 0.5f * tacc : 0.0f;   // sigma = 0.5
        float v = spd * fabsf(cosf(a - uva) + diag) / dd;
        vals[j] = v;
        ssum += v * v;
    }
    __shared__ float red[8];
    #pragma unroll
    for (int o = 16; o > 0; o >>= 1) ssum += __shfl_xor_sync(0xffffffffu, ssum, o);
    if ((tid & 31) == 0) red[tid >> 5] = ssum;
    __syncthreads();
    float tot = 0.0f;
    #pragma unroll
    for (int w = 0; w < 8; w++) tot += red[w];
    float inv = 1.0f / fmaxf(sqrtf(tot), 1e-12f);

    float* swrow = g_SW + (size_t)row * NN;
    __nv_bfloat16* hrow = g_SWh + (size_t)row * NN;
    __nv_bfloat16* lrow = g_SWl + (size_t)row * NN;
    #pragma unroll
    for (int j = 0; j < 4; j++) {
        int m = tid + j * 256;
        float v = vals[j] * inv;
        swrow[m] = v;
        __nv_bfloat16 h = __float2bfloat16(v);
        hrow[m] = h;
        lrow[m] = __float2bfloat16(v - __bfloat162float(h));
    }
}

// ---------------------------------------------------------------------------
// Kernel 3: mma.sync (HMMA) split-bf16 SYRK: hi*hi + hi*lo + lo*hi, fp32 acc.
// MODE 0: C = relu(A A^T), K=2048 -> d_out
// MODE 1: C = 0.07*(SW SW^T) + EPS, K=1024 -> g_Y
// 128x128 tile/CTA, 8 warps (32x64 each), BK=32, cp.async double buffer.
// SMEM tile row stride = 40 bf16 (80 B) -> conflict-free ldmatrix.
// ---------------------------------------------------------------------------
#define ARR_BYTES 10240            // 128 rows * 40 bf16 * 2
#define SYRK_SMEM  (2 * 4 * ARR_BYTES)   // 81920

template <int MODE>
__global__ void __launch_bounds__(256, 1) syrk_mma_kernel(float* __restrict__ Cout)
{
    const int K = (MODE == 0) ? KA : NN;
    const __nv_bfloat16* __restrict__ Xh = (MODE == 0) ? g_Ah : g_SWh;
    const __nv_bfloat16* __restrict__ Xl = (MODE == 0) ? g_Al : g_SWl;
    float* __restrict__ C = (MODE == 0) ? Cout : g_Y;

    extern __shared__ char smem[];
    const uint32_t sbase = smem_u32(smem);
    const int tid = threadIdx.x;
    const int wid = tid >> 5, lane = tid & 31;
    const int wm = wid & 3, wn = wid >> 2;         // warp tile: rows wm*32, cols wn*64

    int pair = blockIdx.x % NPAIRS;
    int b = blockIdx.x / NPAIRS;
    int ti = 0;
    while (pair >= ti + 1) { pair -= (ti + 1); ti++; }
    int tj = pair;                                  // tj <= ti

    const __nv_bfloat16* pAh = Xh + ((size_t)b * NN + ti * 128) * K;
    const __nv_bfloat16* pAl = Xl + ((size_t)b * NN + ti * 128) * K;
    const __nv_bfloat16* pBh = Xh + ((size_t)b * NN + tj * 128) * K;
    const __nv_bfloat16* pBl = Xl + ((size_t)b * NN + tj * 128) * K;

    const int NC = K / 32;

    // ---- async load of one 32-wide K slab into buffer `buf` ----
    auto load_stage = [&](int kt, int buf) {
        const __nv_bfloat16* srcs[4] = { pAh, pBh, pAl, pBl };
        #pragma unroll
        for (int arr = 0; arr < 4; arr++) {
            #pragma unroll
            for (int h = 0; h < 2; h++) {
                int rc = h * 256 + tid;             // 0..511
                int row = rc >> 2, c = rc & 3;
                const void* src = srcs[arr] + (size_t)row * K + kt + c * 8;
                uint32_t dst = sbase + (uint32_t)((buf * 4 + arr) * ARR_BYTES
                                                  + row * 80 + c * 16);
                asm volatile("cp.async.cg.shared.global [%0], [%1], 16;"
                             :: "r"(dst), "l"(src));
            }
        }
    };

    float acc[2][8][4];
    #pragma unroll
    for (int mt = 0; mt < 2; mt++)
        #pragma unroll
        for (int j = 0; j < 8; j++)
            #pragma unroll
            for (int e = 0; e < 4; e++) acc[mt][j][e] = 0.0f;

    load_stage(0, 0);
    asm volatile("cp.async.commit_group;" ::: "memory");
    load_stage(32, 1);
    asm volatile("cp.async.commit_group;" ::: "memory");
    asm volatile("cp.async.wait_group 1;" ::: "memory");
    __syncthreads();

    const int arow = wm * 32 + (lane & 15);
    const int brow = wn * 64 + (lane & 15);
    const int chalf = (lane >> 4) * 8;              // elems

    for (int ck = 0; ck < NC; ck++) {
        int buf = ck & 1;
        uint32_t base0 = sbase + (uint32_t)(buf * 4) * ARR_BYTES;
        #pragma unroll
        for (int ks = 0; ks < 2; ks++) {
            int cbyte = (ks * 16 + chalf) * 2;
            uint32_t ah[2][4], al[2][4], bh[4][4], bl[4][4];
            #pragma unroll
            for (int mt = 0; mt < 2; mt++) {
                uint32_t off = (uint32_t)((arow + mt * 16) * 80 + cbyte);
                ldsm4(ah[mt], base0 + off);                    // Ah
                ldsm4(al[mt], base0 + 2 * ARR_BYTES + off);    // Al
            }
            #pragma unroll
            for (int nt = 0; nt < 4; nt++) {
                uint32_t off = (uint32_t)((brow + nt * 16) * 80 + cbyte);
                ldsm4(bh[nt], base0 + ARR_BYTES + off);        // Bh
                ldsm4(bl[nt], base0 + 3 * ARR_BYTES + off);    // Bl
            }
            #pragma unroll
            for (int mt = 0; mt < 2; mt++)
                #pragma unroll
                for (int j = 0; j < 8; j++) {
                    uint32_t h0 = bh[j >> 1][j & 1], h1 = bh[j >> 1][(j & 1) + 2];
                    uint32_t l0 = bl[j >> 1][j & 1], l1 = bl[j >> 1][(j & 1) + 2];
                    mma16816(acc[mt][j], ah[mt], h0, h1);
                    mma16816(acc[mt][j], ah[mt], l0, l1);
                    mma16816(acc[mt][j], al[mt], h0, h1);
                }
        }
        if (ck + 2 < NC) load_stage((ck + 2) * 32, buf);
        asm volatile("cp.async.commit_group;" ::: "memory");
        asm volatile("cp.async.wait_group 1;" ::: "memory");
        __syncthreads();
    }

    // ---- epilogue: transform, direct store, SMEM-transpose mirror ----
    size_t cb = (size_t)b * NN * NN;
    float* trans = reinterpret_cast<float*>(smem);     // 128 x (stride 132) f32

    #pragma unroll
    for (int mt = 0; mt < 2; mt++)
        #pragma unroll
        for (int j = 0; j < 8; j++)
            #pragma unroll
            for (int rh = 0; rh < 2; rh++) {
                float x0 = acc[mt][j][rh * 2], x1 = acc[mt][j][rh * 2 + 1];
                float v0, v1;
                if (MODE == 0) { v0 = (x0 > 0.0f) ? x0 : 0.0f;
                                 v1 = (x1 > 0.0f) ? x1 : 0.0f; }
                else           { v0 = 0.07f * x0 + EPSF;
                                 v1 = 0.07f * x1 + EPSF; }
                int gmL = wm * 32 + mt * 16 + (lane >> 2) + rh * 8;
                int gnL = wn * 64 + j * 8 + (lane & 3) * 2;
                float2 v2 = make_float2(v0, v1);
                *reinterpret_cast<float2*>(
                    C + cb + (size_t)(ti * 128 + gmL) * NN + tj * 128 + gnL) = v2;
                if (ti != tj) {
                    trans[gnL * 132 + gmL] = v0;
                    trans[(gnL + 1) * 132 + gmL] = v1;
                }
            }
    __syncthreads();

    if (ti != tj) {
        #pragma unroll
        for (int i = 0; i < 16; i++) {
            int flat = tid + i * 256;               // 4096 float4s
            int r = flat >> 5, c4 = flat & 31;
            const float* tr = trans + r * 132 + c4 * 4;
            float4 v = make_float4(tr[0], tr[1], tr[2], tr[3]);
            *reinterpret_cast<float4*>(
                C + cb + (size_t)(tj * 128 + r) * NN + ti * 128 + c4 * 4) = v;
        }
    }
}

// ---------------------------------------------------------------------------
// Kernel 4: per-row: y=l2norm(Y); u=l2norm(|0.5*SW+sqrt(y)|+EPS); out *= u
// ---------------------------------------------------------------------------
__global__ void __launch_bounds__(256) final_kernel(float* __restrict__ out)
{
    int row = blockIdx.x;
    int tid = threadIdx.x;
    const float* yrow = g_Y + (size_t)row * NN;
    const float* swrow = g_SW + (size_t)row * NN;
    float* orow = out + (size_t)row * NN;

    __shared__ float red[8];

    float yv[4];
    float s1 = 0.0f;
    #pragma unroll
    for (int j = 0; j < 4; j++) {
        float y = yrow[tid + j * 256];
        yv[j] = y;
        s1 += y * y;
    }
    #pragma unroll
    for (int o = 16; o > 0; o >>= 1) s1 += __shfl_xor_sync(0xffffffffu, s1, o);
    if ((tid & 31) == 0) red[tid >> 5] = s1;
    __syncthreads();
    float yt = 0.0f;
    #pragma unroll
    for (int w = 0; w < 8; w++) yt += red[w];
    float yin = 1.0f / fmaxf(sqrtf(yt), 1e-12f);
    __syncthreads();

    float tv[4];
    float s2 = 0.0f;
    #pragma unroll
    for (int j = 0; j < 4; j++) {
        float t = fabsf(0.5f * swrow[tid + j * 256] + sqrtf(yv[j] * yin)) + EPSF;
        tv[j] = t;
        s2 += t * t;
    }
    #pragma unroll
    for (int o = 16; o > 0; o >>= 1) s2 += __shfl_xor_sync(0xffffffffu, s2, o);
    if ((tid & 31) == 0) red[tid >> 5] = s2;
    __syncthreads();
    float tt = 0.0f;
    #pragma unroll
    for (int w = 0; w < 8; w++) tt += red[w];
    float tin = 1.0f / fmaxf(sqrtf(tt), 1e-12f);

    #pragma unroll
    for (int j = 0; j < 4; j++) {
        int m = tid + j * 256;
        orow[m] = orow[m] * (tv[j] * tin);
    }
}

// ---------------------------------------------------------------------------
extern "C" void kernel_launch(void* const* d_in, const int* in_sizes, int n_in,
                              void* d_out, int out_size)
{
    const float* context     = (const float*)d_in[0];  // (8,1024,128)
    const float* acc_u       = (const float*)d_in[1];
    const float* acc_v       = (const float*)d_in[2];
    const float* uv_angle    = (const float*)d_in[3];
    const float* uv_angleACC = (const float*)d_in[4];
    const float* speed       = (const float*)d_in[5];
    // d_in[6] = isPhy (unused)
    const float* dist        = (const float*)d_in[7];  // (1024,1024)
    const float* angle       = (const float*)d_in[8];  // (1024,1024)
    const float* weight      = (const float*)d_in[9];  // (16,128)
    float* out = (float*)d_out;                        // (8,1024,1024)

    cudaFuncSetAttribute((const void*)&syrk_mma_kernel<0>,
                         cudaFuncAttributeMaxDynamicSharedMemorySize, SYRK_SMEM);
    cudaFuncSetAttribute((const void*)&syrk_mma_kernel<1>,
                         cudaFuncAttributeMaxDynamicSharedMemorySize, SYRK_SMEM);

    build_A_kernel<<<NB * NN / 4, 128>>>(context, weight);
    selfwind_kernel<<<NB * NN, 256>>>(acc_u, acc_v, uv_angle, uv_angleACC, speed, dist, angle);
    syrk_mma_kernel<0><<<NB * NPAIRS, 256, SYRK_SMEM>>>(out);
    syrk_mma_kernel<1><<<NB * NPAIRS, 256, SYRK_SMEM>>>(out);
    final_kernel<<<NB * NN, 256>>>(out);
}

// round 6
// speedup vs baseline: 2.2746x; 1.0036x over previous
#include <cuda_runtime.h>
#include <cuda_bf16.h>
#include <math.h>
#include <stdint.h>

#define NB 8
#define NN 1024
#define ND 128
#define NP 16
#define KA 2048           // P*D joint contraction dim for attention
#define EPSF 1e-5f
#define NPAIRS 36         // 8*9/2 symmetric tile pairs

// ---------------------------------------------------------------------------
// Scratch (module-load allocated; no runtime allocation)
// ---------------------------------------------------------------------------
__device__ __align__(16) __nv_bfloat16 g_Ah[(size_t)NB * NN * KA];   // 32 MB
__device__ __align__(16) __nv_bfloat16 g_Al[(size_t)NB * NN * KA];   // 32 MB
__device__ __align__(16) float         g_SW[(size_t)NB * NN * NN];   // 32 MB
__device__ __align__(16) __nv_bfloat16 g_SWh[(size_t)NB * NN * NN];  // 16 MB
__device__ __align__(16) __nv_bfloat16 g_SWl[(size_t)NB * NN * NN];  // 16 MB
__device__ __align__(16) float         g_Y[(size_t)NB * NN * NN];    // 32 MB

__device__ __forceinline__ uint32_t smem_u32(const void* p) {
    uint32_t a;
    asm("{ .reg .u64 t; cvta.to.shared.u64 t, %1; cvt.u32.u64 %0, t; }"
        : "=r"(a) : "l"(p));
    return a;
}

__device__ __forceinline__ uint32_t pack_bf2(__nv_bfloat16 a, __nv_bfloat16 b) {
    return (uint32_t)__bfloat16_as_ushort(a) | ((uint32_t)__bfloat16_as_ushort(b) << 16);
}

__device__ __forceinline__ void ldsm4(uint32_t* r, uint32_t addr) {
    asm volatile("ldmatrix.sync.aligned.m8n8.x4.shared.b16 {%0,%1,%2,%3}, [%4];"
                 : "=r"(r[0]), "=r"(r[1]), "=r"(r[2]), "=r"(r[3]) : "r"(addr));
}

__device__ __forceinline__ void mma16816(float* c, const uint32_t* a,
                                         uint32_t b0, uint32_t b1) {
    asm volatile(
        "mma.sync.aligned.m16n8k16.row.col.f32.bf16.bf16.f32 "
        "{%0,%1,%2,%3}, {%4,%5,%6,%7}, {%8,%9}, {%0,%1,%2,%3};"
        : "+f"(c[0]), "+f"(c[1]), "+f"(c[2]), "+f"(c[3])
        : "r"(a[0]), "r"(a[1]), "r"(a[2]), "r"(a[3]), "r"(b0), "r"(b1));
}

// ---------------------------------------------------------------------------
// Kernel 1: hi/lo bf16 split of A[b,n,p*128+d] = ctx*w / (sqrt(P)*||c*w_p||)
// ---------------------------------------------------------------------------
__global__ void __launch_bounds__(128) build_A_kernel(
    const float* __restrict__ context, const float* __restrict__ weight)
{
    __shared__ float wsh[NP * ND];
    int tid = threadIdx.x;
    #pragma unroll
    for (int i = tid; i < NP * ND; i += 128) wsh[i] = weight[i];
    __syncthreads();

    int warp = tid >> 5, lane = tid & 31;
    int row = blockIdx.x * 4 + warp;
    const float4* ctx4 = reinterpret_cast<const float4*>(context + (size_t)row * ND);
    float4 c = ctx4[lane];
    const float4* w4 = reinterpret_cast<const float4*>(wsh);
    uint2* Ah2 = reinterpret_cast<uint2*>(g_Ah + (size_t)row * KA);
    uint2* Al2 = reinterpret_cast<uint2*>(g_Al + (size_t)row * KA);

    #pragma unroll
    for (int p = 0; p < NP; p++) {
        float4 wv = w4[p * 32 + lane];
        float4 pr;
        pr.x = c.x * wv.x; pr.y = c.y * wv.y; pr.z = c.z * wv.z; pr.w = c.w * wv.w;
        float s = pr.x * pr.x + pr.y * pr.y + pr.z * pr.z + pr.w * pr.w;
        #pragma unroll
        for (int o = 16; o > 0; o >>= 1) s += __shfl_xor_sync(0xffffffffu, s, o);
        float inv = 0.25f / fmaxf(sqrtf(s), 1e-12f);   // 0.25 = 1/sqrt(P)
        float v0 = pr.x * inv, v1 = pr.y * inv, v2 = pr.z * inv, v3 = pr.w * inv;
        __nv_bfloat16 h0 = __float2bfloat16(v0), h1 = __float2bfloat16(v1);
        __nv_bfloat16 h2 = __float2bfloat16(v2), h3 = __float2bfloat16(v3);
        uint2 hv; hv.x = pack_bf2(h0, h1); hv.y = pack_bf2(h2, h3);
        Ah2[p * 32 + lane] = hv;
        __nv_bfloat16 l0 = __float2bfloat16(v0 - __bfloat162float(h0));
        __nv_bfloat16 l1 = __float2bfloat16(v1 - __bfloat162float(h1));
        __nv_bfloat16 l2 = __float2bfloat16(v2 - __bfloat162float(h2));
        __nv_bfloat16 l3 = __float2bfloat16(v3 - __bfloat162float(h3));
        uint2 lv; lv.x = pack_bf2(l0, l1); lv.y = pack_bf2(l2, l3);
        Al2[p * 32 + lane] = lv;
    }
}

// ---------------------------------------------------------------------------
// Kernel 2: selfwind rows, L2-normalized; writes fp32 + hi/lo bf16.
// ---------------------------------------------------------------------------
__global__ void __launch_bounds__(256) selfwind_kernel(
    const float* __restrict__ acc_u, const float* __restrict__ acc_v,
    const float* __restrict__ uv_angle, const float* __restrict__ uv_angleACC,
    const float* __restrict__ speed,
    const float* __restrict__ dist, const float* __restrict__ angle)
{
    int row = blockIdx.x;          // b*N + n
    int n = row & (NN - 1);
    int tid = threadIdx.x;

    float uva = uv_angle[row];
    float au = acc_u[row], av = acc_v[row];
    float tacc = sqrtf(au * au + av * av + EPSF) * fabsf(cosf(uv_angleACC[row] - uva));
    float spd = fabsf(speed[row]);

    float vals[4];
    float ssum = 0.0f;
    #pragma unroll
    for (int j = 0; j < 4; j++) {
        int m = tid + j * 256;
        float a = angle[n * NN + m];
        float dd = dist[n * NN + m] + EPSF;
        float diag = (m == n) ? 0.5f * tacc : 0.0f;   // sigma = 0.5
        float v = spd * fabsf(cosf(a - uva) + diag) / dd;
        vals[j] = v;
        ssum += v * v;
    }
    __shared__ float red[8];
    #pragma unroll
    for (int o = 16; o > 0; o >>= 1) ssum += __shfl_xor_sync(0xffffffffu, ssum, o);
    if ((tid & 31) == 0) red[tid >> 5] = ssum;
    __syncthreads();
    float tot = 0.0f;
    #pragma unroll
    for (int w = 0; w < 8; w++) tot += red[w];
    float inv = 1.0f / fmaxf(sqrtf(tot), 1e-12f);

    float* swrow = g_SW + (size_t)row * NN;
    __nv_bfloat16* hrow = g_SWh + (size_t)row * NN;
    __nv_bfloat16* lrow = g_SWl + (size_t)row * NN;
    #pragma unroll
    for (int j = 0; j < 4; j++) {
        int m = tid + j * 256;
        float v = vals[j] * inv;
        swrow[m] = v;
        __nv_bfloat16 h = __float2bfloat16(v);
        hrow[m] = h;
        lrow[m] = __float2bfloat16(v - __bfloat162float(h));
    }
}

// ---------------------------------------------------------------------------
// Kernel 3: mma.sync (HMMA) split-bf16 SYRK: hi*hi + hi*lo + lo*hi, fp32 acc.
// MODE 0: C = relu(A A^T), K=2048 -> d_out
// MODE 1: C = 0.07*(SW SW^T) + EPS, K=1024 -> g_Y
// 128x128 tile/CTA, 8 warps (32x64 each), BK=32, cp.async double buffer.
// 2 CTAs/SM. SMEM row stride = 40 bf16 -> conflict-free ldmatrix.
// RAW-hazard fix: __syncthreads() between compute reads of a buffer and the
// cp.async prefetch that overwrites it.
// ---------------------------------------------------------------------------
#define ARR_BYTES 10240            // 128 rows * 40 bf16 * 2
#define SYRK_SMEM  (2 * 4 * ARR_BYTES)   // 81920

template <int MODE>
__global__ void __launch_bounds__(256, 2) syrk_mma_kernel(float* __restrict__ Cout)
{
    const int K = (MODE == 0) ? KA : NN;
    const __nv_bfloat16* __restrict__ Xh = (MODE == 0) ? g_Ah : g_SWh;
    const __nv_bfloat16* __restrict__ Xl = (MODE == 0) ? g_Al : g_SWl;
    float* __restrict__ C = (MODE == 0) ? Cout : g_Y;

    extern __shared__ char smem[];
    const uint32_t sbase = smem_u32(smem);
    const int tid = threadIdx.x;
    const int wid = tid >> 5, lane = tid & 31;
    const int wm = wid & 3, wn = wid >> 2;         // warp tile: rows wm*32, cols wn*64

    int pair = blockIdx.x % NPAIRS;
    int b = blockIdx.x / NPAIRS;
    int ti = 0;
    while (pair >= ti + 1) { pair -= (ti + 1); ti++; }
    int tj = pair;                                  // tj <= ti

    const __nv_bfloat16* pAh = Xh + ((size_t)b * NN + ti * 128) * K;
    const __nv_bfloat16* pAl = Xl + ((size_t)b * NN + ti * 128) * K;
    const __nv_bfloat16* pBh = Xh + ((size_t)b * NN + tj * 128) * K;
    const __nv_bfloat16* pBl = Xl + ((size_t)b * NN + tj * 128) * K;

    const int NC = K / 32;

    // ---- async load of one 32-wide K slab into buffer `buf` ----
    auto load_stage = [&](int kt, int buf) {
        const __nv_bfloat16* srcs[4] = { pAh, pBh, pAl, pBl };
        #pragma unroll
        for (int arr = 0; arr < 4; arr++) {
            #pragma unroll
            for (int h = 0; h < 2; h++) {
                int rc = h * 256 + tid;             // 0..511
                int row = rc >> 2, c = rc & 3;
                const void* src = srcs[arr] + (size_t)row * K + kt + c * 8;
                uint32_t dst = sbase + (uint32_t)((buf * 4 + arr) * ARR_BYTES
                                                  + row * 80 + c * 16);
                asm volatile("cp.async.cg.shared.global [%0], [%1], 16;"
                             :: "r"(dst), "l"(src));
            }
        }
    };

    float acc[2][8][4];
    #pragma unroll
    for (int mt = 0; mt < 2; mt++)
        #pragma unroll
        for (int j = 0; j < 8; j++)
            #pragma unroll
            for (int e = 0; e < 4; e++) acc[mt][j][e] = 0.0f;

    load_stage(0, 0);
    asm volatile("cp.async.commit_group;" ::: "memory");
    load_stage(32, 1);
    asm volatile("cp.async.commit_group;" ::: "memory");
    asm volatile("cp.async.wait_group 1;" ::: "memory");
    __syncthreads();

    const int arow = wm * 32 + (lane & 15);
    const int brow = wn * 64 + (lane & 15);
    const int chalf = (lane >> 4) * 8;              // elems

    for (int ck = 0; ck < NC; ck++) {
        int buf = ck & 1;
        uint32_t base0 = sbase + (uint32_t)(buf * 4) * ARR_BYTES;
        #pragma unroll
        for (int ks = 0; ks < 2; ks++) {
            int cbyte = (ks * 16 + chalf) * 2;
            uint32_t ah[2][4], al[2][4];
            #pragma unroll
            for (int mt = 0; mt < 2; mt++) {
                uint32_t off = (uint32_t)((arow + mt * 16) * 80 + cbyte);
                ldsm4(ah[mt], base0 + off);                    // Ah
                ldsm4(al[mt], base0 + 2 * ARR_BYTES + off);    // Al
            }
            #pragma unroll
            for (int nt = 0; nt < 4; nt++) {
                uint32_t bh[4], bl[4];
                uint32_t off = (uint32_t)((brow + nt * 16) * 80 + cbyte);
                ldsm4(bh, base0 + ARR_BYTES + off);            // Bh
                ldsm4(bl, base0 + 3 * ARR_BYTES + off);        // Bl
                #pragma unroll
                for (int mt = 0; mt < 2; mt++)
                    #pragma unroll
                    for (int jj = 0; jj < 2; jj++) {
                        float* a = acc[mt][nt * 2 + jj];
                        mma16816(a, ah[mt], bh[jj], bh[jj + 2]);
                        mma16816(a, ah[mt], bl[jj], bl[jj + 2]);
                        mma16816(a, al[mt], bh[jj], bh[jj + 2]);
                    }
            }
        }
        // Drain all reads of `buf` before the prefetch below overwrites it.
        __syncthreads();
        if (ck + 2 < NC) load_stage((ck + 2) * 32, buf);
        asm volatile("cp.async.commit_group;" ::: "memory");
        asm volatile("cp.async.wait_group 1;" ::: "memory");
        __syncthreads();
    }

    // ---- epilogue: transform, direct store, SMEM-transpose mirror ----
    size_t cb = (size_t)b * NN * NN;
    float* trans = reinterpret_cast<float*>(smem);     // 128 x (stride 132) f32

    #pragma unroll
    for (int mt = 0; mt < 2; mt++)
        #pragma unroll
        for (int j = 0; j < 8; j++)
            #pragma unroll
            for (int rh = 0; rh < 2; rh++) {
                float x0 = acc[mt][j][rh * 2], x1 = acc[mt][j][rh * 2 + 1];
                float v0, v1;
                if (MODE == 0) { v0 = (x0 > 0.0f) ? x0 : 0.0f;
                                 v1 = (x1 > 0.0f) ? x1 : 0.0f; }
                else           { v0 = 0.07f * x0 + EPSF;
                                 v1 = 0.07f * x1 + EPSF; }
                int gmL = wm * 32 + mt * 16 + (lane >> 2) + rh * 8;
                int gnL = wn * 64 + j * 8 + (lane & 3) * 2;
                float2 v2 = make_float2(v0, v1);
                *reinterpret_cast<float2*>(
                    C + cb + (size_t)(ti * 128 + gmL) * NN + tj * 128 + gnL) = v2;
                if (ti != tj) {
                    trans[gnL * 132 + gmL] = v0;
                    trans[(gnL + 1) * 132 + gmL] = v1;
                }
            }
    __syncthreads();

    if (ti != tj) {
        #pragma unroll
        for (int i = 0; i < 16; i++) {
            int flat = tid + i * 256;               // 4096 float4s
            int r = flat >> 5, c4 = flat & 31;
            const float* tr = trans + r * 132 + c4 * 4;
            float4 v = make_float4(tr[0], tr[1], tr[2], tr[3]);
            *reinterpret_cast<float4*>(
                C + cb + (size_t)(tj * 128 + r) * NN + ti * 128 + c4 * 4) = v;
        }
    }
}

// ---------------------------------------------------------------------------
// Kernel 4: per-row: y=l2norm(Y); u=l2norm(|0.5*SW+sqrt(y)|+EPS); out *= u
// ---------------------------------------------------------------------------
__global__ void __launch_bounds__(256) final_kernel(float* __restrict__ out)
{
    int row = blockIdx.x;
    int tid = threadIdx.x;
    const float* yrow = g_Y + (size_t)row * NN;
    const float* swrow = g_SW + (size_t)row * NN;
    float* orow = out + (size_t)row * NN;

    __shared__ float red[8];

    float yv[4];
    float s1 = 0.0f;
    #pragma unroll
    for (int j = 0; j < 4; j++) {
        float y = yrow[tid + j * 256];
        yv[j] = y;
        s1 += y * y;
    }
    #pragma unroll
    for (int o = 16; o > 0; o >>= 1) s1 += __shfl_xor_sync(0xffffffffu, s1, o);
    if ((tid & 31) == 0) red[tid >> 5] = s1;
    __syncthreads();
    float yt = 0.0f;
    #pragma unroll
    for (int w = 0; w < 8; w++) yt += red[w];
    float yin = 1.0f / fmaxf(sqrtf(yt), 1e-12f);
    __syncthreads();

    float tv[4];
    float s2 = 0.0f;
    #pragma unroll
    for (int j = 0; j < 4; j++) {
        float t = fabsf(0.5f * swrow[tid + j * 256] + sqrtf(yv[j] * yin)) + EPSF;
        tv[j] = t;
        s2 += t * t;
    }
    #pragma unroll
    for (int o = 16; o > 0; o >>= 1) s2 += __shfl_xor_sync(0xffffffffu, s2, o);
    if ((tid & 31) == 0) red[tid >> 5] = s2;
    __syncthreads();
    float tt = 0.0f;
    #pragma unroll
    for (int w = 0; w < 8; w++) tt += red[w];
    float tin = 1.0f / fmaxf(sqrtf(tt), 1e-12f);

    #pragma unroll
    for (int j = 0; j < 4; j++) {
        int m = tid + j * 256;
        orow[m] = orow[m] * (tv[j] * tin);
    }
}

// ---------------------------------------------------------------------------
extern "C" void kernel_launch(void* const* d_in, const int* in_sizes, int n_in,
                              void* d_out, int out_size)
{
    const float* context     = (const float*)d_in[0];  // (8,1024,128)
    const float* acc_u       = (const float*)d_in[1];
    const float* acc_v       = (const float*)d_in[2];
    const float* uv_angle    = (const float*)d_in[3];
    const float* uv_angleACC = (const float*)d_in[4];
    const float* speed       = (const float*)d_in[5];
    // d_in[6] = isPhy (unused)
    const float* dist        = (const float*)d_in[7];  // (1024,1024)
    const float* angle       = (const float*)d_in[8];  // (1024,1024)
    const float* weight      = (const float*)d_in[9];  // (16,128)
    float* out = (float*)d_out;                        // (8,1024,1024)

    cudaFuncSetAttribute((const void*)&syrk_mma_kernel<0>,
                         cudaFuncAttributeMaxDynamicSharedMemorySize, SYRK_SMEM);
    cudaFuncSetAttribute((const void*)&syrk_mma_kernel<1>,
                         cudaFuncAttributeMaxDynamicSharedMemorySize, SYRK_SMEM);

    build_A_kernel<<<NB * NN / 4, 128>>>(context, weight);
    selfwind_kernel<<<NB * NN, 256>>>(acc_u, acc_v, uv_angle, uv_angleACC, speed, dist, angle);
    syrk_mma_kernel<0><<<NB * NPAIRS, 256, SYRK_SMEM>>>(out);
    syrk_mma_kernel<1><<<NB * NPAIRS, 256, SYRK_SMEM>>>(out);
    final_kernel<<<NB * NN, 256>>>(out);
}

// round 7
// speedup vs baseline: 2.6768x; 1.1768x over previous
#include <cuda_runtime.h>
#include <cuda_bf16.h>
#include <math.h>
#include <stdint.h>

#define NB 8
#define NN 1024
#define ND 128
#define NP 16
#define KA 2048           // P*D joint contraction dim for attention
#define EPSF 1e-5f
#define NPAIRS 36         // 8*9/2 symmetric tile pairs

// ---------------------------------------------------------------------------
// Scratch (module-load allocated; no runtime allocation)
// ---------------------------------------------------------------------------
__device__ __align__(16) __nv_bfloat16 g_Ah[(size_t)NB * NN * KA];   // 32 MB
__device__ __align__(16) __nv_bfloat16 g_Al[(size_t)NB * NN * KA];   // 32 MB
__device__ __align__(16) float         g_SW[(size_t)NB * NN * NN];   // 32 MB
__device__ __align__(16) __nv_bfloat16 g_SWh[(size_t)NB * NN * NN];  // 16 MB
__device__ __align__(16) __nv_bfloat16 g_SWl[(size_t)NB * NN * NN];  // 16 MB
__device__ __align__(16) float         g_Y[(size_t)NB * NN * NN];    // 32 MB

__device__ __forceinline__ uint32_t smem_u32(const void* p) {
    uint32_t a;
    asm("{ .reg .u64 t; cvta.to.shared.u64 t, %1; cvt.u32.u64 %0, t; }"
        : "=r"(a) : "l"(p));
    return a;
}

__device__ __forceinline__ uint32_t pack_bf2(__nv_bfloat16 a, __nv_bfloat16 b) {
    return (uint32_t)__bfloat16_as_ushort(a) | ((uint32_t)__bfloat16_as_ushort(b) << 16);
}

__device__ __forceinline__ void ldsm4(uint32_t* r, uint32_t addr) {
    asm volatile("ldmatrix.sync.aligned.m8n8.x4.shared.b16 {%0,%1,%2,%3}, [%4];"
                 : "=r"(r[0]), "=r"(r[1]), "=r"(r[2]), "=r"(r[3]) : "r"(addr));
}

__device__ __forceinline__ void mma16816(float* c, const uint32_t* a,
                                         uint32_t b0, uint32_t b1) {
    asm volatile(
        "mma.sync.aligned.m16n8k16.row.col.f32.bf16.bf16.f32 "
        "{%0,%1,%2,%3}, {%4,%5,%6,%7}, {%8,%9}, {%0,%1,%2,%3};"
        : "+f"(c[0]), "+f"(c[1]), "+f"(c[2]), "+f"(c[3])
        : "r"(a[0]), "r"(a[1]), "r"(a[2]), "r"(a[3]), "r"(b0), "r"(b1));
}

// Swizzled SMEM address for a (row, chunk) pair inside one 128x32 bf16 array:
// row stride 64B (no padding), 16B chunk c stored at c ^ ((row>>1)&3).
__device__ __forceinline__ uint32_t swz_addr(int row, int c) {
    return (uint32_t)(row * 64 + ((c ^ ((row >> 1) & 3)) << 4));
}

// ---------------------------------------------------------------------------
// Kernel 1: hi/lo bf16 split of A[b,n,p*128+d] = ctx*w / (sqrt(P)*||c*w_p||)
// ---------------------------------------------------------------------------
__global__ void __launch_bounds__(128) build_A_kernel(
    const float* __restrict__ context, const float* __restrict__ weight)
{
    __shared__ float wsh[NP * ND];
    int tid = threadIdx.x;
    #pragma unroll
    for (int i = tid; i < NP * ND; i += 128) wsh[i] = weight[i];
    __syncthreads();

    int warp = tid >> 5, lane = tid & 31;
    int row = blockIdx.x * 4 + warp;
    const float4* ctx4 = reinterpret_cast<const float4*>(context + (size_t)row * ND);
    float4 c = ctx4[lane];
    const float4* w4 = reinterpret_cast<const float4*>(wsh);
    uint2* Ah2 = reinterpret_cast<uint2*>(g_Ah + (size_t)row * KA);
    uint2* Al2 = reinterpret_cast<uint2*>(g_Al + (size_t)row * KA);

    #pragma unroll
    for (int p = 0; p < NP; p++) {
        float4 wv = w4[p * 32 + lane];
        float4 pr;
        pr.x = c.x * wv.x; pr.y = c.y * wv.y; pr.z = c.z * wv.z; pr.w = c.w * wv.w;
        float s = pr.x * pr.x + pr.y * pr.y + pr.z * pr.z + pr.w * pr.w;
        #pragma unroll
        for (int o = 16; o > 0; o >>= 1) s += __shfl_xor_sync(0xffffffffu, s, o);
        float inv = 0.25f / fmaxf(sqrtf(s), 1e-12f);   // 0.25 = 1/sqrt(P)
        float v0 = pr.x * inv, v1 = pr.y * inv, v2 = pr.z * inv, v3 = pr.w * inv;
        __nv_bfloat16 h0 = __float2bfloat16(v0), h1 = __float2bfloat16(v1);
        __nv_bfloat16 h2 = __float2bfloat16(v2), h3 = __float2bfloat16(v3);
        uint2 hv; hv.x = pack_bf2(h0, h1); hv.y = pack_bf2(h2, h3);
        Ah2[p * 32 + lane] = hv;
        __nv_bfloat16 l0 = __float2bfloat16(v0 - __bfloat162float(h0));
        __nv_bfloat16 l1 = __float2bfloat16(v1 - __bfloat162float(h1));
        __nv_bfloat16 l2 = __float2bfloat16(v2 - __bfloat162float(h2));
        __nv_bfloat16 l3 = __float2bfloat16(v3 - __bfloat162float(h3));
        uint2 lv; lv.x = pack_bf2(l0, l1); lv.y = pack_bf2(l2, l3);
        Al2[p * 32 + lane] = lv;
    }
}

// ---------------------------------------------------------------------------
// Kernel 2: selfwind rows, L2-normalized; writes fp32 + hi/lo bf16.
// ---------------------------------------------------------------------------
__global__ void __launch_bounds__(256) selfwind_kernel(
    const float* __restrict__ acc_u, const float* __restrict__ acc_v,
    const float* __restrict__ uv_angle, const float* __restrict__ uv_angleACC,
    const float* __restrict__ speed,
    const float* __restrict__ dist, const float* __restrict__ angle)
{
    int row = blockIdx.x;          // b*N + n
    int n = row & (NN - 1);
    int tid = threadIdx.x;

    float uva = uv_angle[row];
    float au = acc_u[row], av = acc_v[row];
    float tacc = sqrtf(au * au + av * av + EPSF) * fabsf(cosf(uv_angleACC[row] - uva));
    float spd = fabsf(speed[row]);

    float vals[4];
    float ssum = 0.0f;
    #pragma unroll
    for (int j = 0; j < 4; j++) {
        int m = tid + j * 256;
        float a = angle[n * NN + m];
        float dd = dist[n * NN + m] + EPSF;
        float diag = (m == n) ? 0.5f * tacc : 0.0f;   // sigma = 0.5
        float v = spd * fabsf(cosf(a - uva) + diag) / dd;
        vals[j] = v;
        ssum += v * v;
    }
    __shared__ float red[8];
    #pragma unroll
    for (int o = 16; o > 0; o >>= 1) ssum += __shfl_xor_sync(0xffffffffu, ssum, o);
    if ((tid & 31) == 0) red[tid >> 5] = ssum;
    __syncthreads();
    float tot = 0.0f;
    #pragma unroll
    for (int w = 0; w < 8; w++) tot += red[w];
    float inv = 1.0f / fmaxf(sqrtf(tot), 1e-12f);

    float* swrow = g_SW + (size_t)row * NN;
    __nv_bfloat16* hrow = g_SWh + (size_t)row * NN;
    __nv_bfloat16* lrow = g_SWl + (size_t)row * NN;
    #pragma unroll
    for (int j = 0; j < 4; j++) {
        int m = tid + j * 256;
        float v = vals[j] * inv;
        swrow[m] = v;
        __nv_bfloat16 h = __float2bfloat16(v);
        hrow[m] = h;
        lrow[m] = __float2bfloat16(v - __bfloat162float(h));
    }
}

// ---------------------------------------------------------------------------
// Kernel 3: mma.sync (HMMA) split-bf16 SYRK: hi*hi + hi*lo + lo*hi, fp32 acc.
// MODE 0: C = relu(A A^T), K=2048 -> d_out
// MODE 1: C = 0.07*(SW SW^T) + EPS, K=1024 -> g_Y
// 128x128 tile/CTA, 8 warps (32x64 each), BK=32.
// 3-stage cp.async pipeline, ONE __syncthreads per chunk, XOR-swizzled
// zero-padding SMEM layout (stage=32KB), 2 CTAs/SM (192KB total).
// ---------------------------------------------------------------------------
#define ARR_BYTES 8192             // 128 rows * 64 B (32 bf16, no pad)
#define STAGE_BYTES (4 * ARR_BYTES)     // Ah,Bh,Al,Bl = 32768
#define SYRK_SMEM (3 * STAGE_BYTES)     // 98304 (also covers 67.6KB epilogue)

template <int MODE>
__global__ void __launch_bounds__(256, 2) syrk_mma_kernel(float* __restrict__ Cout)
{
    const int K = (MODE == 0) ? KA : NN;
    const __nv_bfloat16* __restrict__ Xh = (MODE == 0) ? g_Ah : g_SWh;
    const __nv_bfloat16* __restrict__ Xl = (MODE == 0) ? g_Al : g_SWl;
    float* __restrict__ C = (MODE == 0) ? Cout : g_Y;

    extern __shared__ char smem[];
    const uint32_t sbase = smem_u32(smem);
    const int tid = threadIdx.x;
    const int wid = tid >> 5, lane = tid & 31;
    const int wm = wid & 3, wn = wid >> 2;         // warp tile: rows wm*32, cols wn*64

    int pair = blockIdx.x % NPAIRS;
    int b = blockIdx.x / NPAIRS;
    int ti = 0;
    while (pair >= ti + 1) { pair -= (ti + 1); ti++; }
    int tj = pair;                                  // tj <= ti

    const __nv_bfloat16* pAh = Xh + ((size_t)b * NN + ti * 128) * K;
    const __nv_bfloat16* pAl = Xl + ((size_t)b * NN + ti * 128) * K;
    const __nv_bfloat16* pBh = Xh + ((size_t)b * NN + tj * 128) * K;
    const __nv_bfloat16* pBl = Xl + ((size_t)b * NN + tj * 128) * K;

    const int NC = K / 32;

    // ---- async load of one 32-wide K slab into stage `st` ----
    // Each thread: 2 rows per array, 16B each (512 chunks / 256 threads / halves).
    const int lrow = tid >> 2;           // 0..63 base row
    const int lc   = tid & 3;            // chunk 0..3
    auto load_stage = [&](int kt, int st) {
        uint32_t stb = sbase + (uint32_t)st * STAGE_BYTES;
        const __nv_bfloat16* srcs[4] = { pAh, pBh, pAl, pBl };
        #pragma unroll
        for (int arr = 0; arr < 4; arr++) {
            #pragma unroll
            for (int h = 0; h < 2; h++) {
                int row = lrow + h * 64;
                const void* src = srcs[arr] + (size_t)row * K + kt + lc * 8;
                uint32_t dst = stb + (uint32_t)arr * ARR_BYTES + swz_addr(row, lc);
                asm volatile("cp.async.cg.shared.global [%0], [%1], 16;"
                             :: "r"(dst), "l"(src));
            }
        }
        asm volatile("cp.async.commit_group;" ::: "memory");
    };

    float acc[2][8][4];
    #pragma unroll
    for (int mt = 0; mt < 2; mt++)
        #pragma unroll
        for (int j = 0; j < 8; j++)
            #pragma unroll
            for (int e = 0; e < 4; e++) acc[mt][j][e] = 0.0f;

    // Prologue: stages 0 and 1 in flight.
    load_stage(0, 0);
    load_stage(32, 1);
    asm volatile("cp.async.wait_group 1;" ::: "memory");   // stage 0 ready
    __syncthreads();

    const int arow = wm * 32 + (lane & 15);
    const int brow = wn * 64 + (lane & 15);
    const int cpart = lane >> 4;                    // which 16B chunk half

    for (int ck = 0; ck < NC; ck++) {
        int st = ck % 3;
        uint32_t stb = sbase + (uint32_t)st * STAGE_BYTES;
        #pragma unroll
        for (int ks = 0; ks < 2; ks++) {
            int c = ks * 2 + cpart;                 // chunk index 0..3
            uint32_t ah[2][4], al[2][4];
            #pragma unroll
            for (int mt = 0; mt < 2; mt++) {
                uint32_t off = swz_addr(arow + mt * 16, c);
                ldsm4(ah[mt], stb + off);                      // Ah
                ldsm4(al[mt], stb + 2 * ARR_BYTES + off);      // Al
            }
            #pragma unroll
            for (int nt = 0; nt < 4; nt++) {
                uint32_t bh[4], bl[4];
                uint32_t off = swz_addr(brow + nt * 16, c);
                ldsm4(bh, stb + ARR_BYTES + off);              // Bh
                ldsm4(bl, stb + 3 * ARR_BYTES + off);          // Bl
                #pragma unroll
                for (int mt = 0; mt < 2; mt++)
                    #pragma unroll
                    for (int jj = 0; jj < 2; jj++) {
                        float* a = acc[mt][nt * 2 + jj];
                        mma16816(a, ah[mt], bh[jj], bh[jj + 2]);
                        mma16816(a, ah[mt], bl[jj], bl[jj + 2]);
                        mma16816(a, al[mt], bh[jj], bh[jj + 2]);
                    }
            }
        }
        // Prefetch stage ck+2 into buffer (ck+2)%3 = (ck-1)%3 (read finished
        // in iter ck-1, ordered by that iteration's barrier).
        if (ck + 2 < NC) load_stage((ck + 2) * 32, (ck + 2) % 3);
        else asm volatile("cp.async.commit_group;" ::: "memory");
        asm volatile("cp.async.wait_group 1;" ::: "memory");   // stage ck+1 ready
        __syncthreads();
    }

    // ---- epilogue: transform, direct store, SMEM-transpose mirror ----
    size_t cb = (size_t)b * NN * NN;
    float* trans = reinterpret_cast<float*>(smem);     // 128 x (stride 132) f32

    #pragma unroll
    for (int mt = 0; mt < 2; mt++)
        #pragma unroll
        for (int j = 0; j < 8; j++)
            #pragma unroll
            for (int rh = 0; rh < 2; rh++) {
                float x0 = acc[mt][j][rh * 2], x1 = acc[mt][j][rh * 2 + 1];
                float v0, v1;
                if (MODE == 0) { v0 = (x0 > 0.0f) ? x0 : 0.0f;
                                 v1 = (x1 > 0.0f) ? x1 : 0.0f; }
                else           { v0 = 0.07f * x0 + EPSF;
                                 v1 = 0.07f * x1 + EPSF; }
                int gmL = wm * 32 + mt * 16 + (lane >> 2) + rh * 8;
                int gnL = wn * 64 + j * 8 + (lane & 3) * 2;
                float2 v2 = make_float2(v0, v1);
                *reinterpret_cast<float2*>(
                    C + cb + (size_t)(ti * 128 + gmL) * NN + tj * 128 + gnL) = v2;
                if (ti != tj) {
                    trans[gnL * 132 + gmL] = v0;
                    trans[(gnL + 1) * 132 + gmL] = v1;
                }
            }
    __syncthreads();

    if (ti != tj) {
        #pragma unroll
        for (int i = 0; i < 16; i++) {
            int flat = tid + i * 256;               // 4096 float4s
            int r = flat >> 5, c4 = flat & 31;
            const float* tr = trans + r * 132 + c4 * 4;
            float4 v = make_float4(tr[0], tr[1], tr[2], tr[3]);
            *reinterpret_cast<float4*>(
                C + cb + (size_t)(tj * 128 + r) * NN + ti * 128 + c4 * 4) = v;
        }
    }
}

// ---------------------------------------------------------------------------
// Kernel 4: per-row: y=l2norm(Y); u=l2norm(|0.5*SW+sqrt(y)|+EPS); out *= u
// ---------------------------------------------------------------------------
__global__ void __launch_bounds__(256) final_kernel(float* __restrict__ out)
{
    int row = blockIdx.x;
    int tid = threadIdx.x;
    const float* yrow = g_Y + (size_t)row * NN;
    const float* swrow = g_SW + (size_t)row * NN;
    float* orow = out + (size_t)row * NN;

    __shared__ float red[8];

    float yv[4];
    float s1 = 0.0f;
    #pragma unroll
    for (int j = 0; j < 4; j++) {
        float y = yrow[tid + j * 256];
        yv[j] = y;
        s1 += y * y;
    }
    #pragma unroll
    for (int o = 16; o > 0; o >>= 1) s1 += __shfl_xor_sync(0xffffffffu, s1, o);
    if ((tid & 31) == 0) red[tid >> 5] = s1;
    __syncthreads();
    float yt = 0.0f;
    #pragma unroll
    for (int w = 0; w < 8; w++) yt += red[w];
    float yin = 1.0f / fmaxf(sqrtf(yt), 1e-12f);
    __syncthreads();

    float tv[4];
    float s2 = 0.0f;
    #pragma unroll
    for (int j = 0; j < 4; j++) {
        float t = fabsf(0.5f * swrow[tid + j * 256] + sqrtf(yv[j] * yin)) + EPSF;
        tv[j] = t;
        s2 += t * t;
    }
    #pragma unroll
    for (int o = 16; o > 0; o >>= 1) s2 += __shfl_xor_sync(0xffffffffu, s2, o);
    if ((tid & 31) == 0) red[tid >> 5] = s2;
    __syncthreads();
    float tt = 0.0f;
    #pragma unroll
    for (int w = 0; w < 8; w++) tt += red[w];
    float tin = 1.0f / fmaxf(sqrtf(tt), 1e-12f);

    #pragma unroll
    for (int j = 0; j < 4; j++) {
        int m = tid + j * 256;
        orow[m] = orow[m] * (tv[j] * tin);
    }
}

// ---------------------------------------------------------------------------
extern "C" void kernel_launch(void* const* d_in, const int* in_sizes, int n_in,
                              void* d_out, int out_size)
{
    const float* context     = (const float*)d_in[0];  // (8,1024,128)
    const float* acc_u       = (const float*)d_in[1];
    const float* acc_v       = (const float*)d_in[2];
    const float* uv_angle    = (const float*)d_in[3];
    const float* uv_angleACC = (const float*)d_in[4];
    const float* speed       = (const float*)d_in[5];
    // d_in[6] = isPhy (unused)
    const float* dist        = (const float*)d_in[7];  // (1024,1024)
    const float* angle       = (const float*)d_in[8];  // (1024,1024)
    const float* weight      = (const float*)d_in[9];  // (16,128)
    float* out = (float*)d_out;                        // (8,1024,1024)

    cudaFuncSetAttribute((const void*)&syrk_mma_kernel<0>,
                         cudaFuncAttributeMaxDynamicSharedMemorySize, SYRK_SMEM);
    cudaFuncSetAttribute((const void*)&syrk_mma_kernel<1>,
                         cudaFuncAttributeMaxDynamicSharedMemorySize, SYRK_SMEM);

    build_A_kernel<<<NB * NN / 4, 128>>>(context, weight);
    selfwind_kernel<<<NB * NN, 256>>>(acc_u, acc_v, uv_angle, uv_angleACC, speed, dist, angle);
    syrk_mma_kernel<0><<<NB * NPAIRS, 256, SYRK_SMEM>>>(out);
    syrk_mma_kernel<1><<<NB * NPAIRS, 256, SYRK_SMEM>>>(out);
    final_kernel<<<NB * NN, 256>>>(out);
}